// round 11
// baseline (speedup 1.0000x reference)
#include <cuda_runtime.h>
#include <math.h>
#include <float.h>
#include <stdint.h>

#define BATCH   2
#define SEQL    2048
#define DIMV    1536
#define NHEADS  12
#define HDIM    128
#define NTOK    (BATCH * SEQL)
#define EPSV    1e-6f

/* ---- scratch ---- */
__device__ float g_q[NTOK * DIMV];
__device__ float g_k[NTOK * DIMV];
__device__ float g_v[NTOK * DIMV];     /* V^T as tf32 bits: [(b*12+h)*128+d][s] */
__device__ float g_att[NTOK * DIMV];   /* attention out as tf32 bits */
__device__ uint32_t g_xt[NTOK * DIMV];       /* x pre-converted to tf32 bits */
__device__ uint32_t c_wq[DIMV * DIMV];
__device__ uint32_t c_wk[DIMV * DIMV];
__device__ uint32_t c_wv[DIMV * DIMV];
__device__ uint32_t c_wo[DIMV * DIMV];

__device__ __forceinline__ uint32_t f2tf(float x) {
    uint32_t u;
    asm("cvt.rna.tf32.f32 %0, %1;" : "=r"(u) : "f"(x));
    return u;
}

__device__ __forceinline__ uint32_t sptr(const void* p) {
    return (uint32_t)__cvta_generic_to_shared(p);
}

__device__ __forceinline__ void cp16(uint32_t dst, const void* src) {
    asm volatile("cp.async.cg.shared.global [%0], [%1], 16;" :: "r"(dst), "l"(src));
}
#define CP_COMMIT() asm volatile("cp.async.commit_group;")
#define CP_WAIT1()  asm volatile("cp.async.wait_group 1;")

/* D += A(m16k8) * B(k8n8), tf32 */
__device__ __forceinline__ void mma8(float* d, const uint32_t* a, const uint32_t* b) {
    asm volatile(
        "mma.sync.aligned.m16n8k8.row.col.f32.tf32.tf32.f32 "
        "{%0,%1,%2,%3},{%4,%5,%6,%7},{%8,%9},{%0,%1,%2,%3};"
        : "+f"(d[0]), "+f"(d[1]), "+f"(d[2]), "+f"(d[3])
        : "r"(a[0]), "r"(a[1]), "r"(a[2]), "r"(a[3]), "r"(b[0]), "r"(b[1]));
}

/* 4 x (8x8 b32) matrices */
__device__ __forceinline__ void ldsm4(uint32_t& r0, uint32_t& r1, uint32_t& r2, uint32_t& r3,
                                      uint32_t addr) {
    asm volatile("ldmatrix.sync.aligned.m8n8.x4.shared.b16 {%0,%1,%2,%3}, [%4];"
                 : "=r"(r0), "=r"(r1), "=r"(r2), "=r"(r3) : "r"(addr));
}

/* =================== pre-conversion kernels =================== */
__global__ __launch_bounds__(256)
void cvt_x_kernel(const float* __restrict__ x, uint32_t* __restrict__ dst)
{
    int i = blockIdx.x * 256 + threadIdx.x;
    float4 v = ((const float4*)x)[i];
    ((uint4*)dst)[i] = make_uint4(f2tf(v.x), f2tf(v.y), f2tf(v.z), f2tf(v.w));
}

__global__ __launch_bounds__(256)
void cvt_w_kernel(const float* __restrict__ wq, const float* __restrict__ wk,
                  const float* __restrict__ wv, const float* __restrict__ wo,
                  uint32_t* __restrict__ dq, uint32_t* __restrict__ dk,
                  uint32_t* __restrict__ dv, uint32_t* __restrict__ dwo)
{
    int z = blockIdx.y;
    const float* s = (z == 0) ? wq : (z == 1) ? wk : (z == 2) ? wv : wo;
    uint32_t* d = (z == 0) ? dq : (z == 1) ? dk : (z == 2) ? dv : dwo;
    int i = blockIdx.x * 256 + threadIdx.x;
    float4 v = ((const float4*)s)[i];
    ((uint4*)d)[i] = make_uint4(f2tf(v.x), f2tf(v.y), f2tf(v.z), f2tf(v.w));
}

/* =================== tf32 GEMM v3: cp.async double-buffered, pre-converted inputs ====== */
/* Y[M,N] = X[M,K] W[N,K]^T + bias ; X,W are tf32 bits */
#define TBK 32
#define XST 36                       /* stride mod 32 == 4: conflict-free frag loads */
#define GST_W (128 * XST)            /* words per matrix per stage: 4608 */
#define GSTAGE_W (2 * GST_W)         /* words per stage: 9216 */
#define GEMM_SMEM (2 * GSTAGE_W * 4) /* 73728 bytes */

__global__ __launch_bounds__(256, 2)
void gemm3_tf32(const uint32_t* __restrict__ X,
                const uint32_t* __restrict__ W0, const uint32_t* __restrict__ W1, const uint32_t* __restrict__ W2,
                const float* __restrict__ B0, const float* __restrict__ B1, const float* __restrict__ B2,
                float* __restrict__ Y0, float* __restrict__ Y1, float* __restrict__ Y2,
                int M, int N, int K, int vtrans)
{
    extern __shared__ uint32_t gsm[];

    const int z = blockIdx.z;
    const uint32_t* W = (z == 0) ? W0 : ((z == 1) ? W1 : W2);
    const float* Bb   = (z == 0) ? B0 : ((z == 1) ? B1 : B2);
    float*       Y    = (z == 0) ? Y0 : ((z == 1) ? Y1 : Y2);

    const int bm = blockIdx.y * 128, bn = blockIdx.x * 128;
    const int tid = threadIdx.x, lane = tid & 31, wid = tid >> 5;
    const int wm = wid >> 2, wn = wid & 3;
    const int g = lane >> 2, t = lane & 3;

    const uint32_t sb = sptr(gsm);
    const int lr = tid >> 3;          /* 0..31 */
    const int lc = (tid & 7) << 2;    /* 0,4,..,28 */

    const uint32_t* Xp = X + (size_t)bm * K;
    const uint32_t* Wp = W + (size_t)bn * K;

    float acc[4][4][4];
#pragma unroll
    for (int i = 0; i < 4; i++)
#pragma unroll
        for (int j = 0; j < 4; j++)
#pragma unroll
            for (int r = 0; r < 4; r++) acc[i][j][r] = 0.f;

    /* prologue: stage 0 */
    {
        uint32_t xs = sb, ws = sb + GST_W * 4;
#pragma unroll
        for (int p = 0; p < 4; p++) {
            int row = lr + p * 32;
            cp16(xs + (uint32_t)((row * XST + lc) * 4), Xp + (size_t)row * K + lc);
            cp16(ws + (uint32_t)((row * XST + lc) * 4), Wp + (size_t)row * K + lc);
        }
        CP_COMMIT();
    }

    const int NK = K / TBK;
    for (int kt = 0; kt < NK; kt++) {
        /* prefetch next stage */
        if (kt + 1 < NK) {
            int k0 = (kt + 1) * TBK;
            uint32_t st = sb + ((kt + 1) & 1) * (GSTAGE_W * 4);
            uint32_t xs = st, ws = st + GST_W * 4;
#pragma unroll
            for (int p = 0; p < 4; p++) {
                int row = lr + p * 32;
                cp16(xs + (uint32_t)((row * XST + lc) * 4), Xp + (size_t)row * K + k0 + lc);
                cp16(ws + (uint32_t)((row * XST + lc) * 4), Wp + (size_t)row * K + k0 + lc);
            }
        }
        CP_COMMIT();
        CP_WAIT1();
        __syncthreads();

        const uint32_t* Xs = gsm + (kt & 1) * GSTAGE_W;
        const uint32_t* Ws = Xs + GST_W;

#pragma unroll
        for (int ks = 0; ks < 4; ks++) {
            const int kk = ks * 8;
            uint32_t af[4][4], bf[4][2];
#pragma unroll
            for (int mt = 0; mt < 4; mt++) {
                int r = wm * 64 + mt * 16 + g;
                af[mt][0] = Xs[r * XST + kk + t];
                af[mt][1] = Xs[(r + 8) * XST + kk + t];
                af[mt][2] = Xs[r * XST + kk + t + 4];
                af[mt][3] = Xs[(r + 8) * XST + kk + t + 4];
            }
#pragma unroll
            for (int nt = 0; nt < 4; nt++) {
                int n = wn * 32 + nt * 8 + g;
                bf[nt][0] = Ws[n * XST + kk + t];
                bf[nt][1] = Ws[n * XST + kk + t + 4];
            }
#pragma unroll
            for (int mt = 0; mt < 4; mt++)
#pragma unroll
                for (int nt = 0; nt < 4; nt++)
                    mma8(acc[mt][nt], af[mt], bf[nt]);
        }
        __syncthreads();
    }

    if (vtrans && z == 2) {
        /* V epilogue: transposed tf32 bits: vt[((b*12+h)*128+dd)*2048 + s] */
        uint32_t* vt = (uint32_t*)Y;
#pragma unroll
        for (int mt = 0; mt < 4; mt++) {
            int r = bm + wm * 64 + mt * 16 + g;
            int bb = r >> 11, s = r & (SEQL - 1);
#pragma unroll
            for (int nt = 0; nt < 4; nt++) {
                int c = bn + wn * 32 + nt * 8 + 2 * t;
                float b0v = Bb[c], b1v = Bb[c + 1];
                size_t base0 = ((size_t)((bb * NHEADS + (c >> 7)) * HDIM + (c & 127))) * SEQL;
                size_t base1 = base0 + SEQL;
                vt[base0 + s]     = f2tf(acc[mt][nt][0] + b0v);
                vt[base0 + s + 8] = f2tf(acc[mt][nt][2] + b0v);
                vt[base1 + s]     = f2tf(acc[mt][nt][1] + b1v);
                vt[base1 + s + 8] = f2tf(acc[mt][nt][3] + b1v);
            }
        }
    } else {
#pragma unroll
        for (int mt = 0; mt < 4; mt++) {
            int r = bm + wm * 64 + mt * 16 + g;
#pragma unroll
            for (int nt = 0; nt < 4; nt++) {
                int c = bn + wn * 32 + nt * 8 + 2 * t;
                float b0v = Bb[c], b1v = Bb[c + 1];
                *(float2*)&Y[(size_t)r * N + c] =
                    make_float2(acc[mt][nt][0] + b0v, acc[mt][nt][1] + b1v);
                *(float2*)&Y[(size_t)(r + 8) * N + c] =
                    make_float2(acc[mt][nt][2] + b0v, acc[mt][nt][3] + b1v);
            }
        }
    }
}

/* =================== RMSNorm + RoPE -> writes tf32 bits in place =================== */
__global__ __launch_bounds__(256)
void rmsnorm_rope_kernel(float* __restrict__ yq, float* __restrict__ yk,
                         const float* __restrict__ gq, const float* __restrict__ gk,
                         const float* __restrict__ freqs)
{
    const int t = blockIdx.x;
    const int s = t & (SEQL - 1);
    const int tid = threadIdx.x;
    float* row = (blockIdx.y == 0 ? yq : yk) + (size_t)t * DIMV;
    const float* g = (blockIdx.y == 0) ? gq : gk;

    float v0[3], v1[3];
    float ss = 0.f;
#pragma unroll
    for (int i = 0; i < 3; i++) {
        int p = tid * 3 + i;
        v0[i] = row[2 * p];
        v1[i] = row[2 * p + 1];
        ss += v0[i] * v0[i] + v1[i] * v1[i];
    }
#pragma unroll
    for (int o = 16; o > 0; o >>= 1) ss += __shfl_xor_sync(0xffffffffu, ss, o);
    __shared__ float red[8];
    if ((tid & 31) == 0) red[tid >> 5] = ss;
    __syncthreads();
    float tot = red[0] + red[1] + red[2] + red[3] + red[4] + red[5] + red[6] + red[7];
    float r = rsqrtf(tot * (1.0f / (float)DIMV) + EPSV);

    uint32_t* rowu = (uint32_t*)row;
    const float* fr = freqs + (size_t)s * (2 * HDIM);
#pragma unroll
    for (int i = 0; i < 3; i++) {
        int p  = tid * 3 + i;
        int d0 = 2 * p;
        int dh = d0 & (HDIM - 1);
        float c  = fr[dh];
        float sn = fr[HDIM + dh];
        float a  = v0[i] * r * g[d0];
        float bb = v1[i] * r * g[d0 + 1];
        rowu[d0]     = f2tf(a * c - bb * sn);
        rowu[d0 + 1] = f2tf(bb * c + a * sn);
    }
}

/* =================== flash attention v2 (unchanged structure; tf32-bit output) ======== */
#define AQ2 128
#define AK2 64
#define QST2 132
#define VST2 68
#define PST2 68
#define AOFF_Q 0
#define AOFF_K (128 * QST2)
#define AOFF_V (AOFF_K + 64 * QST2)
#define AOFF_P (AOFF_V + 128 * VST2)
#define ATT2_WORDS (AOFF_P + 128 * PST2)
#define ATT2_SMEM (ATT2_WORDS * 4)   /* 171008 B */

__global__ __launch_bounds__(256, 1)
void attn_v2(const uint32_t* __restrict__ Q, const uint32_t* __restrict__ Kg,
             const uint32_t* __restrict__ VT, const int* __restrict__ seq_lens,
             uint32_t* __restrict__ O)
{
    extern __shared__ uint32_t sm[];
    uint32_t* Qs = sm + AOFF_Q;
    uint32_t* Ks = sm + AOFF_K;
    uint32_t* Vs = sm + AOFF_V;
    uint32_t* Ps = sm + AOFF_P;

    const int qt = blockIdx.x, h = blockIdx.y, b = blockIdx.z;
    const int kvlen = seq_lens[b];
    const int q0 = qt * AQ2;
    const int tid = threadIdx.x, lane = tid & 31, wid = tid >> 5;
    const int g = lane >> 2, t = lane & 3;
    const int sub = lane >> 3, rrl = lane & 7;
    const int ar = rrl + (sub & 1) * 8;
    const int ac = (sub >> 1) * 4;
    const int rowbase = wid * 16;

    const uint32_t qs_b = sptr(Qs), ks_b = sptr(Ks), vs_b = sptr(Vs), ps_b = sptr(Ps);

    const uint32_t* Qg = Q + ((size_t)(b * SEQL + q0) * DIMV + h * HDIM);
    for (int i = tid; i < AQ2 * 32; i += 256) {
        int r = i >> 5, c4 = (i & 31) << 2;
        *(uint4*)&Qs[r * QST2 + c4] = *(const uint4*)&Qg[(size_t)r * DIMV + c4];
    }

    float o[16][4];
#pragma unroll
    for (int nt = 0; nt < 16; nt++)
#pragma unroll
        for (int r = 0; r < 4; r++) o[nt][r] = 0.f;
    float m0 = -FLT_MAX, m1 = -FLT_MAX, l0 = 0.f, l1 = 0.f;

    const int ktiles = kvlen >> 6;
    const float scale = 0.08838834764831845f;
    const uint32_t* VTg = VT + ((size_t)(b * NHEADS + h) * HDIM) * SEQL;

    for (int kt = 0; kt < ktiles; kt++) {
        const int kb = kt << 6;
        __syncthreads();
        const uint32_t* Kp = Kg + ((size_t)(b * SEQL + kb) * DIMV + h * HDIM);
        for (int i = tid; i < AK2 * 32; i += 256) {
            int r = i >> 5, c4 = (i & 31) << 2;
            *(uint4*)&Ks[r * QST2 + c4] = *(const uint4*)&Kp[(size_t)r * DIMV + c4];
        }
        for (int i = tid; i < HDIM * 16; i += 256) {
            int r = i >> 4, c4 = (i & 15) << 2;
            *(uint4*)&Vs[r * VST2 + c4] = *(const uint4*)&VTg[(size_t)r * SEQL + kb + c4];
        }
        __syncthreads();

        /* ---- S = Q K^T ---- */
        float s[8][4];
#pragma unroll
        for (int nt = 0; nt < 8; nt++)
#pragma unroll
            for (int r = 0; r < 4; r++) s[nt][r] = 0.f;

#pragma unroll
        for (int kk = 0; kk < HDIM; kk += 8) {
            uint32_t af[4];
            ldsm4(af[0], af[1], af[2], af[3],
                  qs_b + (uint32_t)(((rowbase + ar) * QST2 + kk + ac) * 4));
#pragma unroll
            for (int p = 0; p < 4; p++) {
                uint32_t r0, r1, r2, r3;
                ldsm4(r0, r1, r2, r3,
                      ks_b + (uint32_t)(((p * 16 + ar) * QST2 + kk + ac) * 4));
                uint32_t blo[2] = { r0, r2 }, bhi[2] = { r1, r3 };
                mma8(s[2 * p], af, blo);
                mma8(s[2 * p + 1], af, bhi);
            }
        }

        /* ---- register softmax ---- */
        float mx0 = -FLT_MAX, mx1 = -FLT_MAX;
#pragma unroll
        for (int nt = 0; nt < 8; nt++) {
            s[nt][0] *= scale; s[nt][1] *= scale; s[nt][2] *= scale; s[nt][3] *= scale;
            mx0 = fmaxf(mx0, fmaxf(s[nt][0], s[nt][1]));
            mx1 = fmaxf(mx1, fmaxf(s[nt][2], s[nt][3]));
        }
        mx0 = fmaxf(mx0, __shfl_xor_sync(0xffffffffu, mx0, 1));
        mx0 = fmaxf(mx0, __shfl_xor_sync(0xffffffffu, mx0, 2));
        mx1 = fmaxf(mx1, __shfl_xor_sync(0xffffffffu, mx1, 1));
        mx1 = fmaxf(mx1, __shfl_xor_sync(0xffffffffu, mx1, 2));
        float mn0 = fmaxf(m0, mx0), mn1 = fmaxf(m1, mx1);
        float c0 = __expf(m0 - mn0), c1 = __expf(m1 - mn1);
        float sum0 = 0.f, sum1 = 0.f;
#pragma unroll
        for (int nt = 0; nt < 8; nt++) {
            float p0 = __expf(s[nt][0] - mn0);
            float p1 = __expf(s[nt][1] - mn0);
            float p2 = __expf(s[nt][2] - mn1);
            float p3 = __expf(s[nt][3] - mn1);
            sum0 += p0 + p1; sum1 += p2 + p3;
            *(uint2*)&Ps[(rowbase + g) * PST2 + 8 * nt + 2 * t] =
                make_uint2(f2tf(p0), f2tf(p1));
            *(uint2*)&Ps[(rowbase + g + 8) * PST2 + 8 * nt + 2 * t] =
                make_uint2(f2tf(p2), f2tf(p3));
        }
        sum0 += __shfl_xor_sync(0xffffffffu, sum0, 1);
        sum0 += __shfl_xor_sync(0xffffffffu, sum0, 2);
        sum1 += __shfl_xor_sync(0xffffffffu, sum1, 1);
        sum1 += __shfl_xor_sync(0xffffffffu, sum1, 2);
        l0 = l0 * c0 + sum0; l1 = l1 * c1 + sum1;
        m0 = mn0; m1 = mn1;
#pragma unroll
        for (int nt = 0; nt < 16; nt++) {
            o[nt][0] *= c0; o[nt][1] *= c0; o[nt][2] *= c1; o[nt][3] *= c1;
        }
        __syncwarp();

        /* ---- O += P V ---- */
#pragma unroll
        for (int kk = 0; kk < AK2; kk += 8) {
            uint32_t af[4];
            ldsm4(af[0], af[1], af[2], af[3],
                  ps_b + (uint32_t)(((rowbase + ar) * PST2 + kk + ac) * 4));
#pragma unroll
            for (int p = 0; p < 8; p++) {
                uint32_t r0, r1, r2, r3;
                ldsm4(r0, r1, r2, r3,
                      vs_b + (uint32_t)(((p * 16 + ar) * VST2 + kk + ac) * 4));
                uint32_t blo[2] = { r0, r2 }, bhi[2] = { r1, r3 };
                mma8(o[2 * p], af, blo);
                mma8(o[2 * p + 1], af, bhi);
            }
        }
    }

    /* epilogue: write tf32 bits (O-proj consumes pre-converted input) */
    const float i0 = 1.0f / l0, i1 = 1.0f / l1;
    const size_t rbase0 = (size_t)(b * SEQL + q0 + rowbase + g) * DIMV + h * HDIM;
    const size_t rbase1 = rbase0 + 8 * DIMV;
#pragma unroll
    for (int nt = 0; nt < 16; nt++) {
        int c = 8 * nt + 2 * t;
        *(uint2*)&O[rbase0 + c] = make_uint2(f2tf(o[nt][0] * i0), f2tf(o[nt][1] * i0));
        *(uint2*)&O[rbase1 + c] = make_uint2(f2tf(o[nt][2] * i1), f2tf(o[nt][3] * i1));
    }
}

/* =================== launch =================== */
extern "C" void kernel_launch(void* const* d_in, const int* in_sizes, int n_in,
                              void* d_out, int out_size)
{
    const float* x     = (const float*)d_in[0];
    const float* wq    = (const float*)d_in[1];
    const float* bq    = (const float*)d_in[2];
    const float* wk    = (const float*)d_in[3];
    const float* bk    = (const float*)d_in[4];
    const float* wv    = (const float*)d_in[5];
    const float* bv    = (const float*)d_in[6];
    const float* wo    = (const float*)d_in[7];
    const float* bo    = (const float*)d_in[8];
    const float* gq    = (const float*)d_in[9];
    const float* gk    = (const float*)d_in[10];
    const float* freqs = (const float*)d_in[11];
    const int*   seq_lens = (const int*)d_in[12];
    float* out = (float*)d_out;

    float *qp, *kp, *vp, *ap;
    uint32_t *xt, *cwq, *cwk, *cwv, *cwo;
    cudaGetSymbolAddress((void**)&qp, g_q);
    cudaGetSymbolAddress((void**)&kp, g_k);
    cudaGetSymbolAddress((void**)&vp, g_v);
    cudaGetSymbolAddress((void**)&ap, g_att);
    cudaGetSymbolAddress((void**)&xt, g_xt);
    cudaGetSymbolAddress((void**)&cwq, c_wq);
    cudaGetSymbolAddress((void**)&cwk, c_wk);
    cudaGetSymbolAddress((void**)&cwv, c_wv);
    cudaGetSymbolAddress((void**)&cwo, c_wo);

    cudaFuncSetAttribute(attn_v2,
                         cudaFuncAttributeMaxDynamicSharedMemorySize, ATT2_SMEM);
    cudaFuncSetAttribute(gemm3_tf32,
                         cudaFuncAttributeMaxDynamicSharedMemorySize, GEMM_SMEM);

    /* one-time tf32 conversion of x and all weights */
    cvt_x_kernel<<<NTOK * DIMV / 4 / 256, 256>>>(x, xt);
    cvt_w_kernel<<<dim3(DIMV * DIMV / 4 / 256, 4), 256>>>(
        wq, wk, wv, wo, cwq, cwk, cwv, cwo);

    /* QKV projection (cp.async pipelined); V epilogue writes transposed tf32 V^T */
    gemm3_tf32<<<dim3(DIMV / 128, NTOK / 128, 3), 256, GEMM_SMEM>>>(
        xt, cwq, cwk, cwv, bq, bk, bv, qp, kp, vp, NTOK, DIMV, DIMV, 1);

    /* RMSNorm + RoPE on q and k, writes tf32 bits in place */
    rmsnorm_rope_kernel<<<dim3(NTOK, 2), 256>>>(qp, kp, gq, gk, freqs);

    attn_v2<<<dim3(SEQL / AQ2, NHEADS, BATCH), 256, ATT2_SMEM>>>(
        (const uint32_t*)qp, (const uint32_t*)kp, (const uint32_t*)vp, seq_lens,
        (uint32_t*)ap);

    /* output projection */
    gemm3_tf32<<<dim3(DIMV / 128, NTOK / 128, 1), 256, GEMM_SMEM>>>(
        (const uint32_t*)ap, cwo, cwo, cwo, bo, bo, bo, out, out, out,
        NTOK, DIMV, DIMV, 0);
}

// round 15
// speedup vs baseline: 1.3957x; 1.3957x over previous
#include <cuda_runtime.h>
#include <math.h>
#include <float.h>
#include <stdint.h>

#define BATCH   2
#define SEQL    2048
#define DIMV    1536
#define NHEADS  12
#define HDIM    128
#define NTOK    (BATCH * SEQL)
#define EPSV    1e-6f

/* ---- scratch ---- */
__device__ float g_q[NTOK * DIMV];
__device__ float g_k[NTOK * DIMV];
__device__ float g_v[NTOK * DIMV];     /* V^T as tf32 bits: [(b*12+h)*128+d][s] */
__device__ float g_att[NTOK * DIMV];   /* attention out as tf32 bits */
__device__ uint32_t g_xt[NTOK * DIMV]; /* x pre-converted to tf32 bits */
__device__ uint32_t c_wq[DIMV * DIMV];
__device__ uint32_t c_wk[DIMV * DIMV];
__device__ uint32_t c_wv[DIMV * DIMV];
__device__ uint32_t c_wo[DIMV * DIMV];

__device__ __forceinline__ uint32_t f2tf(float x) {
    uint32_t u;
    asm("cvt.rna.tf32.f32 %0, %1;" : "=r"(u) : "f"(x));
    return u;
}

__device__ __forceinline__ uint32_t sptr(const void* p) {
    return (uint32_t)__cvta_generic_to_shared(p);
}

/* D += A(m16k8) * B(k8n8), tf32 */
__device__ __forceinline__ void mma8(float* d, const uint32_t* a, const uint32_t* b) {
    asm volatile(
        "mma.sync.aligned.m16n8k8.row.col.f32.tf32.tf32.f32 "
        "{%0,%1,%2,%3},{%4,%5,%6,%7},{%8,%9},{%0,%1,%2,%3};"
        : "+f"(d[0]), "+f"(d[1]), "+f"(d[2]), "+f"(d[3])
        : "r"(a[0]), "r"(a[1]), "r"(a[2]), "r"(a[3]), "r"(b[0]), "r"(b[1]));
}

/* 4 x (8x8 b32) matrices */
__device__ __forceinline__ void ldsm4(uint32_t& r0, uint32_t& r1, uint32_t& r2, uint32_t& r3,
                                      uint32_t addr) {
    asm volatile("ldmatrix.sync.aligned.m8n8.x4.shared.b16 {%0,%1,%2,%3}, [%4];"
                 : "=r"(r0), "=r"(r1), "=r"(r2), "=r"(r3) : "r"(addr));
}

/* =================== pre-conversion kernels =================== */
__global__ __launch_bounds__(256)
void cvt_x_kernel(const float* __restrict__ x, uint32_t* __restrict__ dst)
{
    int i = blockIdx.x * 256 + threadIdx.x;
    float4 v = ((const float4*)x)[i];
    ((uint4*)dst)[i] = make_uint4(f2tf(v.x), f2tf(v.y), f2tf(v.z), f2tf(v.w));
}

__global__ __launch_bounds__(256)
void cvt_w_kernel(const float* __restrict__ wq, const float* __restrict__ wk,
                  const float* __restrict__ wv, const float* __restrict__ wo,
                  uint32_t* __restrict__ dq, uint32_t* __restrict__ dk,
                  uint32_t* __restrict__ dv, uint32_t* __restrict__ dwo)
{
    int z = blockIdx.y;
    const float* s = (z == 0) ? wq : (z == 1) ? wk : (z == 2) ? wv : wo;
    uint32_t* d = (z == 0) ? dq : (z == 1) ? dk : (z == 2) ? dv : dwo;
    int i = blockIdx.x * 256 + threadIdx.x;
    float4 v = ((const float4*)s)[i];
    ((uint4*)d)[i] = make_uint4(f2tf(v.x), f2tf(v.y), f2tf(v.z), f2tf(v.w));
}

/* =================== tf32 GEMM (R10-proven structure, pre-converted inputs) ====== */
/* Y[M,N] = X[M,K] W[N,K]^T + bias ; X,W are tf32 bits */
#define TBK 32
#define XST 36   /* stride mod 32 == 4: conflict-free frag loads, 16B-aligned rows */

__global__ __launch_bounds__(256, 2)
void gemm3_tf32(const uint32_t* __restrict__ X,
                const uint32_t* __restrict__ W0, const uint32_t* __restrict__ W1, const uint32_t* __restrict__ W2,
                const float* __restrict__ B0, const float* __restrict__ B1, const float* __restrict__ B2,
                float* __restrict__ Y0, float* __restrict__ Y1, float* __restrict__ Y2,
                int M, int N, int K, int vtrans)
{
    __shared__ uint32_t Xs[128 * XST];
    __shared__ uint32_t Ws[128 * XST];

    const int z = blockIdx.z;
    const uint32_t* W = (z == 0) ? W0 : ((z == 1) ? W1 : W2);
    const float* Bb   = (z == 0) ? B0 : ((z == 1) ? B1 : B2);
    float*       Y    = (z == 0) ? Y0 : ((z == 1) ? Y1 : Y2);

    const int bm = blockIdx.y * 128, bn = blockIdx.x * 128;
    const int tid = threadIdx.x, lane = tid & 31, wid = tid >> 5;
    const int wm = wid >> 2, wn = wid & 3;
    const int g = lane >> 2, t = lane & 3;

    float acc[4][4][4];
#pragma unroll
    for (int i = 0; i < 4; i++)
#pragma unroll
        for (int j = 0; j < 4; j++)
#pragma unroll
            for (int r = 0; r < 4; r++) acc[i][j][r] = 0.f;

    const int lr = tid >> 3;          /* 0..31 */
    const int lc = (tid & 7) << 2;    /* 0,4,..,28 */

    const uint32_t* Xp = X + (size_t)bm * K;
    const uint32_t* Wp = W + (size_t)bn * K;

    for (int k0 = 0; k0 < K; k0 += TBK) {
#pragma unroll
        for (int p = 0; p < 4; p++) {
            int row = lr + p * 32;
            *(uint4*)&Xs[row * XST + lc] = *(const uint4*)&Xp[(size_t)row * K + k0 + lc];
            *(uint4*)&Ws[row * XST + lc] = *(const uint4*)&Wp[(size_t)row * K + k0 + lc];
        }
        __syncthreads();

#pragma unroll
        for (int ks = 0; ks < 4; ks++) {
            const int kk = ks * 8;
            uint32_t af[4][4], bf[4][2];
#pragma unroll
            for (int mt = 0; mt < 4; mt++) {
                int r = wm * 64 + mt * 16 + g;
                af[mt][0] = Xs[r * XST + kk + t];
                af[mt][1] = Xs[(r + 8) * XST + kk + t];
                af[mt][2] = Xs[r * XST + kk + t + 4];
                af[mt][3] = Xs[(r + 8) * XST + kk + t + 4];
            }
#pragma unroll
            for (int nt = 0; nt < 4; nt++) {
                int n = wn * 32 + nt * 8 + g;
                bf[nt][0] = Ws[n * XST + kk + t];
                bf[nt][1] = Ws[n * XST + kk + t + 4];
            }
#pragma unroll
            for (int mt = 0; mt < 4; mt++)
#pragma unroll
                for (int nt = 0; nt < 4; nt++)
                    mma8(acc[mt][nt], af[mt], bf[nt]);
        }
        __syncthreads();
    }

    if (vtrans && z == 2) {
        /* V epilogue: transposed tf32 bits: vt[((b*12+h)*128+dd)*2048 + s] */
        uint32_t* vt = (uint32_t*)Y;
#pragma unroll
        for (int mt = 0; mt < 4; mt++) {
            int r = bm + wm * 64 + mt * 16 + g;
            int bb = r >> 11, s = r & (SEQL - 1);
#pragma unroll
            for (int nt = 0; nt < 4; nt++) {
                int c = bn + wn * 32 + nt * 8 + 2 * t;
                float b0v = Bb[c], b1v = Bb[c + 1];
                size_t base0 = ((size_t)((bb * NHEADS + (c >> 7)) * HDIM + (c & 127))) * SEQL;
                size_t base1 = base0 + SEQL;
                vt[base0 + s]     = f2tf(acc[mt][nt][0] + b0v);
                vt[base0 + s + 8] = f2tf(acc[mt][nt][2] + b0v);
                vt[base1 + s]     = f2tf(acc[mt][nt][1] + b1v);
                vt[base1 + s + 8] = f2tf(acc[mt][nt][3] + b1v);
            }
        }
    } else {
#pragma unroll
        for (int mt = 0; mt < 4; mt++) {
            int r = bm + wm * 64 + mt * 16 + g;
#pragma unroll
            for (int nt = 0; nt < 4; nt++) {
                int c = bn + wn * 32 + nt * 8 + 2 * t;
                float b0v = Bb[c], b1v = Bb[c + 1];
                *(float2*)&Y[(size_t)r * N + c] =
                    make_float2(acc[mt][nt][0] + b0v, acc[mt][nt][1] + b1v);
                *(float2*)&Y[(size_t)(r + 8) * N + c] =
                    make_float2(acc[mt][nt][2] + b0v, acc[mt][nt][3] + b1v);
            }
        }
    }
}

/* =================== RMSNorm + RoPE -> writes tf32 bits in place =================== */
__global__ __launch_bounds__(256)
void rmsnorm_rope_kernel(float* __restrict__ yq, float* __restrict__ yk,
                         const float* __restrict__ gq, const float* __restrict__ gk,
                         const float* __restrict__ freqs)
{
    const int t = blockIdx.x;
    const int s = t & (SEQL - 1);
    const int tid = threadIdx.x;
    float* row = (blockIdx.y == 0 ? yq : yk) + (size_t)t * DIMV;
    const float* g = (blockIdx.y == 0) ? gq : gk;

    float v0[3], v1[3];
    float ss = 0.f;
#pragma unroll
    for (int i = 0; i < 3; i++) {
        int p = tid * 3 + i;
        v0[i] = row[2 * p];
        v1[i] = row[2 * p + 1];
        ss += v0[i] * v0[i] + v1[i] * v1[i];
    }
#pragma unroll
    for (int o = 16; o > 0; o >>= 1) ss += __shfl_xor_sync(0xffffffffu, ss, o);
    __shared__ float red[8];
    if ((tid & 31) == 0) red[tid >> 5] = ss;
    __syncthreads();
    float tot = red[0] + red[1] + red[2] + red[3] + red[4] + red[5] + red[6] + red[7];
    float r = rsqrtf(tot * (1.0f / (float)DIMV) + EPSV);

    uint32_t* rowu = (uint32_t*)row;
    const float* fr = freqs + (size_t)s * (2 * HDIM);
#pragma unroll
    for (int i = 0; i < 3; i++) {
        int p  = tid * 3 + i;
        int d0 = 2 * p;
        int dh = d0 & (HDIM - 1);
        float c  = fr[dh];
        float sn = fr[HDIM + dh];
        float a  = v0[i] * r * g[d0];
        float bb = v1[i] * r * g[d0 + 1];
        rowu[d0]     = f2tf(a * c - bb * sn);
        rowu[d0 + 1] = f2tf(bb * c + a * sn);
    }
}

/* =================== flash attention v2 (tf32-bit output) ======== */
#define AQ2 128
#define AK2 64
#define QST2 132
#define VST2 68
#define PST2 68
#define AOFF_Q 0
#define AOFF_K (128 * QST2)
#define AOFF_V (AOFF_K + 64 * QST2)
#define AOFF_P (AOFF_V + 128 * VST2)
#define ATT2_WORDS (AOFF_P + 128 * PST2)
#define ATT2_SMEM (ATT2_WORDS * 4)   /* 171008 B */

__global__ __launch_bounds__(256, 1)
void attn_v2(const uint32_t* __restrict__ Q, const uint32_t* __restrict__ Kg,
             const uint32_t* __restrict__ VT, const int* __restrict__ seq_lens,
             uint32_t* __restrict__ O)
{
    extern __shared__ uint32_t sm[];
    uint32_t* Qs = sm + AOFF_Q;
    uint32_t* Ks = sm + AOFF_K;
    uint32_t* Vs = sm + AOFF_V;
    uint32_t* Ps = sm + AOFF_P;

    const int qt = blockIdx.x, h = blockIdx.y, b = blockIdx.z;
    const int kvlen = seq_lens[b];
    const int q0 = qt * AQ2;
    const int tid = threadIdx.x, lane = tid & 31, wid = tid >> 5;
    const int g = lane >> 2, t = lane & 3;
    const int sub = lane >> 3, rrl = lane & 7;
    const int ar = rrl + (sub & 1) * 8;
    const int ac = (sub >> 1) * 4;
    const int rowbase = wid * 16;

    const uint32_t qs_b = sptr(Qs), ks_b = sptr(Ks), vs_b = sptr(Vs), ps_b = sptr(Ps);

    const uint32_t* Qg = Q + ((size_t)(b * SEQL + q0) * DIMV + h * HDIM);
    for (int i = tid; i < AQ2 * 32; i += 256) {
        int r = i >> 5, c4 = (i & 31) << 2;
        *(uint4*)&Qs[r * QST2 + c4] = *(const uint4*)&Qg[(size_t)r * DIMV + c4];
    }

    float o[16][4];
#pragma unroll
    for (int nt = 0; nt < 16; nt++)
#pragma unroll
        for (int r = 0; r < 4; r++) o[nt][r] = 0.f;
    float m0 = -FLT_MAX, m1 = -FLT_MAX, l0 = 0.f, l1 = 0.f;

    const int ktiles = kvlen >> 6;
    const float scale = 0.08838834764831845f;
    const uint32_t* VTg = VT + ((size_t)(b * NHEADS + h) * HDIM) * SEQL;

    for (int kt = 0; kt < ktiles; kt++) {
        const int kb = kt << 6;
        __syncthreads();
        const uint32_t* Kp = Kg + ((size_t)(b * SEQL + kb) * DIMV + h * HDIM);
        for (int i = tid; i < AK2 * 32; i += 256) {
            int r = i >> 5, c4 = (i & 31) << 2;
            *(uint4*)&Ks[r * QST2 + c4] = *(const uint4*)&Kp[(size_t)r * DIMV + c4];
        }
        for (int i = tid; i < HDIM * 16; i += 256) {
            int r = i >> 4, c4 = (i & 15) << 2;
            *(uint4*)&Vs[r * VST2 + c4] = *(const uint4*)&VTg[(size_t)r * SEQL + kb + c4];
        }
        __syncthreads();

        /* ---- S = Q K^T ---- */
        float s[8][4];
#pragma unroll
        for (int nt = 0; nt < 8; nt++)
#pragma unroll
            for (int r = 0; r < 4; r++) s[nt][r] = 0.f;

#pragma unroll
        for (int kk = 0; kk < HDIM; kk += 8) {
            uint32_t af[4];
            ldsm4(af[0], af[1], af[2], af[3],
                  qs_b + (uint32_t)(((rowbase + ar) * QST2 + kk + ac) * 4));
#pragma unroll
            for (int p = 0; p < 4; p++) {
                uint32_t r0, r1, r2, r3;
                ldsm4(r0, r1, r2, r3,
                      ks_b + (uint32_t)(((p * 16 + ar) * QST2 + kk + ac) * 4));
                uint32_t blo[2] = { r0, r2 }, bhi[2] = { r1, r3 };
                mma8(s[2 * p], af, blo);
                mma8(s[2 * p + 1], af, bhi);
            }
        }

        /* ---- register softmax ---- */
        float mx0 = -FLT_MAX, mx1 = -FLT_MAX;
#pragma unroll
        for (int nt = 0; nt < 8; nt++) {
            s[nt][0] *= scale; s[nt][1] *= scale; s[nt][2] *= scale; s[nt][3] *= scale;
            mx0 = fmaxf(mx0, fmaxf(s[nt][0], s[nt][1]));
            mx1 = fmaxf(mx1, fmaxf(s[nt][2], s[nt][3]));
        }
        mx0 = fmaxf(mx0, __shfl_xor_sync(0xffffffffu, mx0, 1));
        mx0 = fmaxf(mx0, __shfl_xor_sync(0xffffffffu, mx0, 2));
        mx1 = fmaxf(mx1, __shfl_xor_sync(0xffffffffu, mx1, 1));
        mx1 = fmaxf(mx1, __shfl_xor_sync(0xffffffffu, mx1, 2));
        float mn0 = fmaxf(m0, mx0), mn1 = fmaxf(m1, mx1);
        float c0 = __expf(m0 - mn0), c1 = __expf(m1 - mn1);
        float sum0 = 0.f, sum1 = 0.f;
#pragma unroll
        for (int nt = 0; nt < 8; nt++) {
            float p0 = __expf(s[nt][0] - mn0);
            float p1 = __expf(s[nt][1] - mn0);
            float p2 = __expf(s[nt][2] - mn1);
            float p3 = __expf(s[nt][3] - mn1);
            sum0 += p0 + p1; sum1 += p2 + p3;
            *(uint2*)&Ps[(rowbase + g) * PST2 + 8 * nt + 2 * t] =
                make_uint2(f2tf(p0), f2tf(p1));
            *(uint2*)&Ps[(rowbase + g + 8) * PST2 + 8 * nt + 2 * t] =
                make_uint2(f2tf(p2), f2tf(p3));
        }
        sum0 += __shfl_xor_sync(0xffffffffu, sum0, 1);
        sum0 += __shfl_xor_sync(0xffffffffu, sum0, 2);
        sum1 += __shfl_xor_sync(0xffffffffu, sum1, 1);
        sum1 += __shfl_xor_sync(0xffffffffu, sum1, 2);
        l0 = l0 * c0 + sum0; l1 = l1 * c1 + sum1;
        m0 = mn0; m1 = mn1;
#pragma unroll
        for (int nt = 0; nt < 16; nt++) {
            o[nt][0] *= c0; o[nt][1] *= c0; o[nt][2] *= c1; o[nt][3] *= c1;
        }
        __syncwarp();

        /* ---- O += P V ---- */
#pragma unroll
        for (int kk = 0; kk < AK2; kk += 8) {
            uint32_t af[4];
            ldsm4(af[0], af[1], af[2], af[3],
                  ps_b + (uint32_t)(((rowbase + ar) * PST2 + kk + ac) * 4));
#pragma unroll
            for (int p = 0; p < 8; p++) {
                uint32_t r0, r1, r2, r3;
                ldsm4(r0, r1, r2, r3,
                      vs_b + (uint32_t)(((p * 16 + ar) * VST2 + kk + ac) * 4));
                uint32_t blo[2] = { r0, r2 }, bhi[2] = { r1, r3 };
                mma8(o[2 * p], af, blo);
                mma8(o[2 * p + 1], af, bhi);
            }
        }
    }

    /* epilogue: write tf32 bits (O-proj consumes pre-converted input) */
    const float i0 = 1.0f / l0, i1 = 1.0f / l1;
    const size_t rbase0 = (size_t)(b * SEQL + q0 + rowbase + g) * DIMV + h * HDIM;
    const size_t rbase1 = rbase0 + 8 * DIMV;
#pragma unroll
    for (int nt = 0; nt < 16; nt++) {
        int c = 8 * nt + 2 * t;
        *(uint2*)&O[rbase0 + c] = make_uint2(f2tf(o[nt][0] * i0), f2tf(o[nt][1] * i0));
        *(uint2*)&O[rbase1 + c] = make_uint2(f2tf(o[nt][2] * i1), f2tf(o[nt][3] * i1));
    }
}

/* =================== launch =================== */
extern "C" void kernel_launch(void* const* d_in, const int* in_sizes, int n_in,
                              void* d_out, int out_size)
{
    const float* x     = (const float*)d_in[0];
    const float* wq    = (const float*)d_in[1];
    const float* bq    = (const float*)d_in[2];
    const float* wk    = (const float*)d_in[3];
    const float* bk    = (const float*)d_in[4];
    const float* wv    = (const float*)d_in[5];
    const float* bv    = (const float*)d_in[6];
    const float* wo    = (const float*)d_in[7];
    const float* bo    = (const float*)d_in[8];
    const float* gq    = (const float*)d_in[9];
    const float* gk    = (const float*)d_in[10];
    const float* freqs = (const float*)d_in[11];
    const int*   seq_lens = (const int*)d_in[12];
    float* out = (float*)d_out;

    float *qp, *kp, *vp, *ap;
    uint32_t *xt, *cwq, *cwk, *cwv, *cwo;
    cudaGetSymbolAddress((void**)&qp, g_q);
    cudaGetSymbolAddress((void**)&kp, g_k);
    cudaGetSymbolAddress((void**)&vp, g_v);
    cudaGetSymbolAddress((void**)&ap, g_att);
    cudaGetSymbolAddress((void**)&xt, g_xt);
    cudaGetSymbolAddress((void**)&cwq, c_wq);
    cudaGetSymbolAddress((void**)&cwk, c_wk);
    cudaGetSymbolAddress((void**)&cwv, c_wv);
    cudaGetSymbolAddress((void**)&cwo, c_wo);

    cudaFuncSetAttribute(attn_v2,
                         cudaFuncAttributeMaxDynamicSharedMemorySize, ATT2_SMEM);

    /* one-time tf32 conversion of x and all weights */
    cvt_x_kernel<<<NTOK * DIMV / 4 / 256, 256>>>(x, xt);
    cvt_w_kernel<<<dim3(DIMV * DIMV / 4 / 256, 4), 256>>>(
        wq, wk, wv, wo, cwq, cwk, cwv, cwo);

    /* QKV projection; V epilogue writes transposed tf32 V^T into g_v */
    gemm3_tf32<<<dim3(DIMV / 128, NTOK / 128, 3), 256>>>(
        xt, cwq, cwk, cwv, bq, bk, bv, qp, kp, vp, NTOK, DIMV, DIMV, 1);

    /* RMSNorm + RoPE on q and k, writes tf32 bits in place */
    rmsnorm_rope_kernel<<<dim3(NTOK, 2), 256>>>(qp, kp, gq, gk, freqs);

    attn_v2<<<dim3(SEQL / AQ2, NHEADS, BATCH), 256, ATT2_SMEM>>>(
        (const uint32_t*)qp, (const uint32_t*)kp, (const uint32_t*)vp, seq_lens,
        (uint32_t*)ap);

    /* output projection */
    gemm3_tf32<<<dim3(DIMV / 128, NTOK / 128, 1), 256>>>(
        (const uint32_t*)ap, cwo, cwo, cwo, bo, bo, bo, out, out, out,
        NTOK, DIMV, DIMV, 0);
}